// round 15
// baseline (speedup 1.0000x reference)
#include <cuda_runtime.h>
#include <cstddef>

// Feature_Embedding (FFM pairwise field interactions) — TERMINAL KERNEL
// x: (4096,16) int32; W: (16,100000,64) fp32; out: (4096, 8704) fp32.
//
// HBM-wall kernel, confirmed over 14 rounds (7 repeats of this exact
// binary: kernel 55.33-56.45 us, bench 61.92-62.24 us — stationary noise).
// DRAM traffic is at the compulsory floor (~330 MB: 187 MB first-touch
// gather rows — L2 dedup of duplicate indices measured complete — plus
// 143 MB mandatory fp32 output) at ~5.9-6.0 TB/s, the HBM3e operating
// point for random 256B-granule reads mixed with a streamed write. Reads
// are dense fully-covered 256B blocks (no over-fetch); the LTS/HBM
// ceiling is path-independent (LDG = TMA = cp.async). Runtime invariant
// (+-1%) to occupancy, MLP, barriers, granularity, CTA fusion, and store
// policy; read/write phase separation regresses 21%.
//
// Shape: one CTA per batch row; 16 float4 lanes x 16 unit stripes;
// uniform pair/diag datapath (diag multiplies by constant ones); 3 units
// (6x LDG.128) batched in flight per thread; barrier-free index broadcast
// via shfl; evict-first streaming stores.

constexpr int F_FIELDS = 16;
constexpr int V_VOCAB  = 100000;
constexpr int N_PAIRS  = 120;
constexpr int N_UNITS  = 136;            // 120 pairs + 16 diag
constexpr int OUT_F4   = N_UNITS * 16;   // 2176 float4 per row
constexpr int ROW_F4   = 16;             // 64 floats = 16 float4

// c_pair[u] = i | (j<<8), triu k=1 row-major
__constant__ unsigned short c_pair[N_PAIRS] = {
    0x0100,0x0200,0x0300,0x0400,0x0500,0x0600,0x0700,0x0800,
    0x0900,0x0A00,0x0B00,0x0C00,0x0D00,0x0E00,0x0F00,
    0x0201,0x0301,0x0401,0x0501,0x0601,0x0701,0x0801,0x0901,
    0x0A01,0x0B01,0x0C01,0x0D01,0x0E01,0x0F01,
    0x0302,0x0402,0x0502,0x0602,0x0702,0x0802,0x0902,0x0A02,
    0x0B02,0x0C02,0x0D02,0x0E02,0x0F02,
    0x0403,0x0503,0x0603,0x0703,0x0803,0x0903,0x0A03,0x0B03,
    0x0C03,0x0D03,0x0E03,0x0F03,
    0x0504,0x0604,0x0704,0x0804,0x0904,0x0A04,0x0B04,0x0C04,
    0x0D04,0x0E04,0x0F04,
    0x0605,0x0705,0x0805,0x0905,0x0A05,0x0B05,0x0C05,0x0D05,
    0x0E05,0x0F05,
    0x0706,0x0806,0x0906,0x0A06,0x0B06,0x0C06,0x0D06,0x0E06,0x0F06,
    0x0807,0x0907,0x0A07,0x0B07,0x0C07,0x0D07,0x0E07,0x0F07,
    0x0908,0x0A08,0x0B08,0x0C08,0x0D08,0x0E08,0x0F08,
    0x0A09,0x0B09,0x0C09,0x0D09,0x0E09,0x0F09,
    0x0B0A,0x0C0A,0x0D0A,0x0E0A,0x0F0A,
    0x0C0B,0x0D0B,0x0E0B,0x0F0B,
    0x0D0C,0x0E0C,0x0F0C,
    0x0E0D,0x0F0D,
    0x0F0E
};

__global__ __launch_bounds__(256, 5)
void ffm_interact_kernel(const int* __restrict__ x,
                         const float* __restrict__ W,
                         float* __restrict__ out)
{
    const int tid  = threadIdx.x;
    const int b    = blockIdx.x;
    const int lane = tid & (ROW_F4 - 1);   // float4 lane within 64-dim row
    const int w    = tid >> 4;             // unit stripe base (0..15)
    const int lid  = tid & 31;

    // each warp loads the 16-field index row; broadcast via shuffle
    const int myx = __ldg(&x[b * F_FIELDS + (lid & 15)]);

    const float4* __restrict__ W4 = reinterpret_cast<const float4*>(W);
    float4* __restrict__ out4 =
        reinterpret_cast<float4*>(out) + (size_t)b * OUT_F4;

    #pragma unroll
    for (int g = 0; g < 3; ++g) {
        float4 va[3], vb[3];
        int    uu[3];
        // address gen + loads: up to 6 independent LDG.128 in flight
        #pragma unroll
        for (int k = 0; k < 3; ++k) {
            const int u = w + (g * 3 + k) * 16;
            uu[k] = u;
            if (u < N_PAIRS) {
                const unsigned int pt = c_pair[u];
                const int i = (int)(pt & 0xFF);
                const int j = (int)(pt >> 8);
                const int xi = __shfl_sync(0xFFFFFFFFu, myx, i);
                const int xj = __shfl_sync(0xFFFFFFFFu, myx, j);
                va[k] = __ldg(W4 + ((size_t)j * V_VOCAB + (size_t)xi) * ROW_F4 + lane);
                vb[k] = __ldg(W4 + ((size_t)i * V_VOCAB + (size_t)xj) * ROW_F4 + lane);
            } else if (u < N_UNITS) {
                const int f = u - N_PAIRS;
                const int xf = __shfl_sync(0xFFFFFFFFu, myx, f);
                va[k] = __ldg(W4 + ((size_t)f * V_VOCAB + (size_t)xf) * ROW_F4 + lane);
                vb[k] = make_float4(1.f, 1.f, 1.f, 1.f);
            }
        }
        // consume + streaming stores
        #pragma unroll
        for (int k = 0; k < 3; ++k) {
            if (uu[k] < N_UNITS) {
                float4 r;
                r.x = va[k].x * vb[k].x;
                r.y = va[k].y * vb[k].y;
                r.z = va[k].z * vb[k].z;
                r.w = va[k].w * vb[k].w;
                __stcs(&out4[(size_t)uu[k] * ROW_F4 + lane], r);
            }
        }
    }
}

extern "C" void kernel_launch(void* const* d_in, const int* in_sizes, int n_in,
                              void* d_out, int out_size)
{
    const int*   x = (const int*)d_in[0];
    const float* W = (const float*)d_in[1];
    float*       o = (float*)d_out;

    const int B = in_sizes[0] / F_FIELDS;   // 4096

    ffm_interact_kernel<<<B, 256>>>(x, W, o);
}

// round 16
// speedup vs baseline: 1.0005x; 1.0005x over previous
#include <cuda_runtime.h>
#include <cstddef>

// Feature_Embedding (FFM pairwise field interactions) — TERMINAL KERNEL
// x: (4096,16) int32; W: (16,100000,64) fp32; out: (4096, 8704) fp32.
//
// HBM-wall kernel, confirmed over 15 rounds (8 repeats of this exact
// binary: kernel 55.33-56.45 us, bench 61.92-62.24 us — stationary noise).
// DRAM traffic is at the compulsory floor (~330 MB: 187 MB first-touch
// gather rows — L2 dedup of duplicate indices measured complete — plus
// 143 MB mandatory fp32 output) at ~5.9-6.0 TB/s, the HBM3e operating
// point for random 256B-granule reads mixed with a streamed write. Reads
// are dense fully-covered 256B blocks (no over-fetch); the LTS/HBM
// ceiling is path-independent (LDG = TMA = cp.async). Runtime invariant
// (+-1%) to occupancy, MLP, barriers, granularity, CTA fusion, and store
// policy; read/write phase separation regresses 21%.
//
// Shape: one CTA per batch row; 16 float4 lanes x 16 unit stripes;
// uniform pair/diag datapath (diag multiplies by constant ones); 3 units
// (6x LDG.128) batched in flight per thread; barrier-free index broadcast
// via shfl; evict-first streaming stores.

constexpr int F_FIELDS = 16;
constexpr int V_VOCAB  = 100000;
constexpr int N_PAIRS  = 120;
constexpr int N_UNITS  = 136;            // 120 pairs + 16 diag
constexpr int OUT_F4   = N_UNITS * 16;   // 2176 float4 per row
constexpr int ROW_F4   = 16;             // 64 floats = 16 float4

// c_pair[u] = i | (j<<8), triu k=1 row-major
__constant__ unsigned short c_pair[N_PAIRS] = {
    0x0100,0x0200,0x0300,0x0400,0x0500,0x0600,0x0700,0x0800,
    0x0900,0x0A00,0x0B00,0x0C00,0x0D00,0x0E00,0x0F00,
    0x0201,0x0301,0x0401,0x0501,0x0601,0x0701,0x0801,0x0901,
    0x0A01,0x0B01,0x0C01,0x0D01,0x0E01,0x0F01,
    0x0302,0x0402,0x0502,0x0602,0x0702,0x0802,0x0902,0x0A02,
    0x0B02,0x0C02,0x0D02,0x0E02,0x0F02,
    0x0403,0x0503,0x0603,0x0703,0x0803,0x0903,0x0A03,0x0B03,
    0x0C03,0x0D03,0x0E03,0x0F03,
    0x0504,0x0604,0x0704,0x0804,0x0904,0x0A04,0x0B04,0x0C04,
    0x0D04,0x0E04,0x0F04,
    0x0605,0x0705,0x0805,0x0905,0x0A05,0x0B05,0x0C05,0x0D05,
    0x0E05,0x0F05,
    0x0706,0x0806,0x0906,0x0A06,0x0B06,0x0C06,0x0D06,0x0E06,0x0F06,
    0x0807,0x0907,0x0A07,0x0B07,0x0C07,0x0D07,0x0E07,0x0F07,
    0x0908,0x0A08,0x0B08,0x0C08,0x0D08,0x0E08,0x0F08,
    0x0A09,0x0B09,0x0C09,0x0D09,0x0E09,0x0F09,
    0x0B0A,0x0C0A,0x0D0A,0x0E0A,0x0F0A,
    0x0C0B,0x0D0B,0x0E0B,0x0F0B,
    0x0D0C,0x0E0C,0x0F0C,
    0x0E0D,0x0F0D,
    0x0F0E
};

__global__ __launch_bounds__(256, 5)
void ffm_interact_kernel(const int* __restrict__ x,
                         const float* __restrict__ W,
                         float* __restrict__ out)
{
    const int tid  = threadIdx.x;
    const int b    = blockIdx.x;
    const int lane = tid & (ROW_F4 - 1);   // float4 lane within 64-dim row
    const int w    = tid >> 4;             // unit stripe base (0..15)
    const int lid  = tid & 31;

    // each warp loads the 16-field index row; broadcast via shuffle
    const int myx = __ldg(&x[b * F_FIELDS + (lid & 15)]);

    const float4* __restrict__ W4 = reinterpret_cast<const float4*>(W);
    float4* __restrict__ out4 =
        reinterpret_cast<float4*>(out) + (size_t)b * OUT_F4;

    #pragma unroll
    for (int g = 0; g < 3; ++g) {
        float4 va[3], vb[3];
        int    uu[3];
        // address gen + loads: up to 6 independent LDG.128 in flight
        #pragma unroll
        for (int k = 0; k < 3; ++k) {
            const int u = w + (g * 3 + k) * 16;
            uu[k] = u;
            if (u < N_PAIRS) {
                const unsigned int pt = c_pair[u];
                const int i = (int)(pt & 0xFF);
                const int j = (int)(pt >> 8);
                const int xi = __shfl_sync(0xFFFFFFFFu, myx, i);
                const int xj = __shfl_sync(0xFFFFFFFFu, myx, j);
                va[k] = __ldg(W4 + ((size_t)j * V_VOCAB + (size_t)xi) * ROW_F4 + lane);
                vb[k] = __ldg(W4 + ((size_t)i * V_VOCAB + (size_t)xj) * ROW_F4 + lane);
            } else if (u < N_UNITS) {
                const int f = u - N_PAIRS;
                const int xf = __shfl_sync(0xFFFFFFFFu, myx, f);
                va[k] = __ldg(W4 + ((size_t)f * V_VOCAB + (size_t)xf) * ROW_F4 + lane);
                vb[k] = make_float4(1.f, 1.f, 1.f, 1.f);
            }
        }
        // consume + streaming stores
        #pragma unroll
        for (int k = 0; k < 3; ++k) {
            if (uu[k] < N_UNITS) {
                float4 r;
                r.x = va[k].x * vb[k].x;
                r.y = va[k].y * vb[k].y;
                r.z = va[k].z * vb[k].z;
                r.w = va[k].w * vb[k].w;
                __stcs(&out4[(size_t)uu[k] * ROW_F4 + lane], r);
            }
        }
    }
}

extern "C" void kernel_launch(void* const* d_in, const int* in_sizes, int n_in,
                              void* d_out, int out_size)
{
    const int*   x = (const int*)d_in[0];
    const float* W = (const float*)d_in[1];
    float*       o = (float*)d_out;

    const int B = in_sizes[0] / F_FIELDS;   // 4096

    ffm_interact_kernel<<<B, 256>>>(x, W, o);
}

// round 17
// speedup vs baseline: 1.0093x; 1.0088x over previous
#include <cuda_runtime.h>
#include <cstddef>

// Feature_Embedding (FFM pairwise field interactions) — TERMINAL KERNEL
// x: (4096,16) int32; W: (16,100000,64) fp32; out: (4096, 8704) fp32.
//
// HBM-wall kernel, confirmed over 16 rounds (9 repeats of this exact
// binary: kernel 55.33-56.45 us, bench 61.92-62.24 us — stationary noise).
// DRAM traffic is at the compulsory floor (~330 MB: 187 MB first-touch
// gather rows — L2 dedup of duplicate indices measured complete — plus
// 143 MB mandatory fp32 output) at ~5.9-6.0 TB/s, the HBM3e operating
// point for random 256B-granule reads mixed with a streamed write. Reads
// are dense fully-covered 256B blocks (no over-fetch); the LTS/HBM
// ceiling is path-independent (LDG = TMA = cp.async). Runtime invariant
// (+-1%) to occupancy, MLP, barriers, granularity, CTA fusion, and store
// policy; read/write phase separation regresses 21%.
//
// Shape: one CTA per batch row; 16 float4 lanes x 16 unit stripes;
// uniform pair/diag datapath (diag multiplies by constant ones); 3 units
// (6x LDG.128) batched in flight per thread; barrier-free index broadcast
// via shfl; evict-first streaming stores.

constexpr int F_FIELDS = 16;
constexpr int V_VOCAB  = 100000;
constexpr int N_PAIRS  = 120;
constexpr int N_UNITS  = 136;            // 120 pairs + 16 diag
constexpr int OUT_F4   = N_UNITS * 16;   // 2176 float4 per row
constexpr int ROW_F4   = 16;             // 64 floats = 16 float4

// c_pair[u] = i | (j<<8), triu k=1 row-major
__constant__ unsigned short c_pair[N_PAIRS] = {
    0x0100,0x0200,0x0300,0x0400,0x0500,0x0600,0x0700,0x0800,
    0x0900,0x0A00,0x0B00,0x0C00,0x0D00,0x0E00,0x0F00,
    0x0201,0x0301,0x0401,0x0501,0x0601,0x0701,0x0801,0x0901,
    0x0A01,0x0B01,0x0C01,0x0D01,0x0E01,0x0F01,
    0x0302,0x0402,0x0502,0x0602,0x0702,0x0802,0x0902,0x0A02,
    0x0B02,0x0C02,0x0D02,0x0E02,0x0F02,
    0x0403,0x0503,0x0603,0x0703,0x0803,0x0903,0x0A03,0x0B03,
    0x0C03,0x0D03,0x0E03,0x0F03,
    0x0504,0x0604,0x0704,0x0804,0x0904,0x0A04,0x0B04,0x0C04,
    0x0D04,0x0E04,0x0F04,
    0x0605,0x0705,0x0805,0x0905,0x0A05,0x0B05,0x0C05,0x0D05,
    0x0E05,0x0F05,
    0x0706,0x0806,0x0906,0x0A06,0x0B06,0x0C06,0x0D06,0x0E06,0x0F06,
    0x0807,0x0907,0x0A07,0x0B07,0x0C07,0x0D07,0x0E07,0x0F07,
    0x0908,0x0A08,0x0B08,0x0C08,0x0D08,0x0E08,0x0F08,
    0x0A09,0x0B09,0x0C09,0x0D09,0x0E09,0x0F09,
    0x0B0A,0x0C0A,0x0D0A,0x0E0A,0x0F0A,
    0x0C0B,0x0D0B,0x0E0B,0x0F0B,
    0x0D0C,0x0E0C,0x0F0C,
    0x0E0D,0x0F0D,
    0x0F0E
};

__global__ __launch_bounds__(256, 5)
void ffm_interact_kernel(const int* __restrict__ x,
                         const float* __restrict__ W,
                         float* __restrict__ out)
{
    const int tid  = threadIdx.x;
    const int b    = blockIdx.x;
    const int lane = tid & (ROW_F4 - 1);   // float4 lane within 64-dim row
    const int w    = tid >> 4;             // unit stripe base (0..15)
    const int lid  = tid & 31;

    // each warp loads the 16-field index row; broadcast via shuffle
    const int myx = __ldg(&x[b * F_FIELDS + (lid & 15)]);

    const float4* __restrict__ W4 = reinterpret_cast<const float4*>(W);
    float4* __restrict__ out4 =
        reinterpret_cast<float4*>(out) + (size_t)b * OUT_F4;

    #pragma unroll
    for (int g = 0; g < 3; ++g) {
        float4 va[3], vb[3];
        int    uu[3];
        // address gen + loads: up to 6 independent LDG.128 in flight
        #pragma unroll
        for (int k = 0; k < 3; ++k) {
            const int u = w + (g * 3 + k) * 16;
            uu[k] = u;
            if (u < N_PAIRS) {
                const unsigned int pt = c_pair[u];
                const int i = (int)(pt & 0xFF);
                const int j = (int)(pt >> 8);
                const int xi = __shfl_sync(0xFFFFFFFFu, myx, i);
                const int xj = __shfl_sync(0xFFFFFFFFu, myx, j);
                va[k] = __ldg(W4 + ((size_t)j * V_VOCAB + (size_t)xi) * ROW_F4 + lane);
                vb[k] = __ldg(W4 + ((size_t)i * V_VOCAB + (size_t)xj) * ROW_F4 + lane);
            } else if (u < N_UNITS) {
                const int f = u - N_PAIRS;
                const int xf = __shfl_sync(0xFFFFFFFFu, myx, f);
                va[k] = __ldg(W4 + ((size_t)f * V_VOCAB + (size_t)xf) * ROW_F4 + lane);
                vb[k] = make_float4(1.f, 1.f, 1.f, 1.f);
            }
        }
        // consume + streaming stores
        #pragma unroll
        for (int k = 0; k < 3; ++k) {
            if (uu[k] < N_UNITS) {
                float4 r;
                r.x = va[k].x * vb[k].x;
                r.y = va[k].y * vb[k].y;
                r.z = va[k].z * vb[k].z;
                r.w = va[k].w * vb[k].w;
                __stcs(&out4[(size_t)uu[k] * ROW_F4 + lane], r);
            }
        }
    }
}

extern "C" void kernel_launch(void* const* d_in, const int* in_sizes, int n_in,
                              void* d_out, int out_size)
{
    const int*   x = (const int*)d_in[0];
    const float* W = (const float*)d_in[1];
    float*       o = (float*)d_out;

    const int B = in_sizes[0] / F_FIELDS;   // 4096

    ffm_interact_kernel<<<B, 256>>>(x, W, o);
}